// round 2
// baseline (speedup 1.0000x reference)
#include <cuda_runtime.h>
#include <cstdint>

// Bayer mosaic channel select:
//   out[b,i,j] = img[b, c, i, j]
//   c = 1 if (i+j) even; else 2 if i even; else 0
// Row-parity view:
//   i even: j even -> ch1, j odd -> ch2
//   i odd : j even -> ch0, j odd -> ch1
// Each thread produces 8 consecutive output floats (two float4 stores),
// reading 2 float4 from each of the two relevant channel planes.
// 4 independent LDG.128 in flight per thread; streaming cache hints since
// there is zero reuse (384 MB streamed through L2 once).

static constexpr int B = 8;
static constexpr int C = 3;
static constexpr int H = 2048;
static constexpr int W = 2048;

__global__ __launch_bounds__(256)
void bayer_kernel(const float* __restrict__ img, float* __restrict__ out) {
    const int W8 = W / 8;                       // 256 eight-float groups per row
    int64_t gid = (int64_t)blockIdx.x * blockDim.x + threadIdx.x;
    int j8 = (int)(gid % W8);
    int64_t bi = gid / W8;                      // b*H + i
    int i = (int)(bi % H);
    int b = (int)(bi / H);

    // Channels for this row: cA serves even j, cB serves odd j
    int cA, cB;
    if ((i & 1) == 0) { cA = 1; cB = 2; }
    else              { cA = 0; cB = 1; }

    const int64_t plane = (int64_t)H * W;
    const int64_t row_base = (int64_t)b * C * plane + (int64_t)i * W + (int64_t)j8 * 8;
    const float* pA = img + row_base + (int64_t)cA * plane;
    const float* pB = img + row_base + (int64_t)cB * plane;

    // 4 independent 128-bit streaming loads
    const float4 a0 = __ldcs(reinterpret_cast<const float4*>(pA));
    const float4 b0 = __ldcs(reinterpret_cast<const float4*>(pB));
    const float4 a1 = __ldcs(reinterpret_cast<const float4*>(pA) + 1);
    const float4 b1 = __ldcs(reinterpret_cast<const float4*>(pB) + 1);

    float4 o0, o1;
    o0.x = a0.x;  o0.y = b0.y;  o0.z = a0.z;  o0.w = b0.w;
    o1.x = a1.x;  o1.y = b1.y;  o1.z = a1.z;  o1.w = b1.w;

    float* po = out + ((int64_t)b * H + i) * W + (int64_t)j8 * 8;
    __stcs(reinterpret_cast<float4*>(po), o0);
    __stcs(reinterpret_cast<float4*>(po) + 1, o1);
}

extern "C" void kernel_launch(void* const* d_in, const int* in_sizes, int n_in,
                              void* d_out, int out_size) {
    const float* img = (const float*)d_in[0];
    float* out = (float*)d_out;

    const int64_t total8 = (int64_t)B * H * (W / 8);   // 4,194,304 threads
    const int threads = 256;
    const int blocks = (int)((total8 + threads - 1) / threads);  // 16384
    bayer_kernel<<<blocks, threads>>>(img, out);
}